// round 15
// baseline (speedup 1.0000x reference)
#include <cuda_runtime.h>
#include <cstdint>

#define NB    2048
#define INS   512
#define SEQL  128
#define NH    12
#define NOUT  3
#define NPRE  1024     // producer blocks
#define NSCAN 256      // consumer blocks (8 batches each)

// scratch (allocation-free contract: __device__ globals)
__device__ float g_pre0[(size_t)NB * SEQL * NH];   // [b][s][h], K-half 0
__device__ float g_pre1[(size_t)NB * SEQL * NH];   // [b][s][h], K-half 1
__device__ int   g_flag[NSCAN];                    // zero-init; reset by consumers

__device__ __forceinline__ unsigned long long fma2(unsigned long long a,
                                                   unsigned long long b,
                                                   unsigned long long c) {
    unsigned long long d;
    asm("fma.rn.f32x2 %0, %1, %2, %3;" : "=l"(d) : "l"(a), "l"(b), "l"(c));
    return d;
}
__device__ __forceinline__ unsigned long long pk2(float f) {
    unsigned long long u;
    asm("mov.b64 %0, {%1, %1};" : "=l"(u) : "f"(f));
    return u;
}
__device__ __forceinline__ float ftanh(float x) {
    float e = __expf(2.0f * x);
    return 1.0f - __fdividef(2.0f, e + 1.0f);
}

// ---------------------------------------------------------------------------
// ONE kernel, 1280 blocks.
//   bid < 1024 : PRE producer (R14 body): px=bid>>1 (4 batches), py=bid&1
//                (K-half). Signals g_flag[bid>>2] with release semantics.
//   bid >= 1024: SCAN consumer g=bid-1024 (batches 8g..8g+7): stages ws/e127
//                + computes h_bwd (independent of pre), then acquires the
//                flag (4 producers), runs the smem-staged recurrence on
//                L2-hot pre data, FC epilogue, resets the flag (replay-safe).
// Blocks schedule ~in bid order, so consumer g arrives as its producers
// (bids 4g..4g+3) retire: scan hides under pre instead of serializing after.
// ---------------------------------------------------------------------------
extern "C" __global__ void __launch_bounds__(128, 5)
mega_kernel(const int* __restrict__ x, const float* __restrict__ emb,
            const float* __restrict__ wih,
            const float* __restrict__ wir, const float* __restrict__ bir,
            const float* __restrict__ bhr,
            const float* __restrict__ whh, const float* __restrict__ bih,
            const float* __restrict__ bhh, const float* __restrict__ fcw,
            const float* __restrict__ fcb, float* __restrict__ out) {
    __shared__ __align__(16) char sraw[38912];   // union: pre 12KB | scan 38KB
    const int tid = threadIdx.x;
    const int bid = blockIdx.x;

    if (bid < NPRE) {
        // ==================== PRE producer ====================
        float2* w2 = (float2*)sraw;              // 12 KB: this K-half only
        const int px = bid >> 1;
        const int py = bid & 1;
        const int ibase = py * 256;

        for (int t = tid; t < 256 * 6; t += 128) {
            int il = t & 255;
            int k = t >> 8;                      // 0..5
            w2[il * 6 + k] = make_float2(wih[(2 * k) * INS + ibase + il],
                                         wih[(2 * k + 1) * INS + ibase + il]);
        }
        __syncthreads();

        const int warp = tid >> 5;
        const int lane = tid & 31;
        const int b = px * 4 + warp;
        const int4* xg = (const int4*)(x + (size_t)b * INS) + py * 64;
        const float* ebase = emb + 4 * lane;

        unsigned long long aa[4][6];             // [s-slot][h-pair]
#pragma unroll
        for (int sp = 0; sp < 4; sp++)
#pragma unroll
            for (int k = 0; k < 6; k++) aa[sp][k] = 0ull;

        float4 eA[4], eB[4];
        int4 qB_cur, qA_next, qB_next, qA_nn;

#define LOADE(buf, q)                                                         \
    do {                                                                      \
        buf[0] = *(const float4*)(ebase + ((unsigned)(q).x << 7));            \
        buf[1] = *(const float4*)(ebase + ((unsigned)(q).y << 7));            \
        buf[2] = *(const float4*)(ebase + ((unsigned)(q).z << 7));            \
        buf[3] = *(const float4*)(ebase + ((unsigned)(q).w << 7));            \
    } while (0)

#define COMPUTE4(buf, bi)                                                     \
    do {                                                                      \
        _Pragma("unroll")                                                     \
        for (int u = 0; u < 4; u++) {                                         \
            unsigned long long p0 = pk2(buf[u].x);                            \
            unsigned long long p1 = pk2(buf[u].y);                            \
            unsigned long long p2 = pk2(buf[u].z);                            \
            unsigned long long p3 = pk2(buf[u].w);                            \
            const ulonglong2* wv =                                            \
                (const ulonglong2*)(w2 + (unsigned)((bi) + u) * 6);           \
            ulonglong2 wA = wv[0], wB = wv[1], wC = wv[2];                    \
            aa[0][0] = fma2(p0, wA.x, aa[0][0]);                              \
            aa[1][0] = fma2(p1, wA.x, aa[1][0]);                              \
            aa[2][0] = fma2(p2, wA.x, aa[2][0]);                              \
            aa[3][0] = fma2(p3, wA.x, aa[3][0]);                              \
            aa[0][1] = fma2(p0, wA.y, aa[0][1]);                              \
            aa[1][1] = fma2(p1, wA.y, aa[1][1]);                              \
            aa[2][1] = fma2(p2, wA.y, aa[2][1]);                              \
            aa[3][1] = fma2(p3, wA.y, aa[3][1]);                              \
            aa[0][2] = fma2(p0, wB.x, aa[0][2]);                              \
            aa[1][2] = fma2(p1, wB.x, aa[1][2]);                              \
            aa[2][2] = fma2(p2, wB.x, aa[2][2]);                              \
            aa[3][2] = fma2(p3, wB.x, aa[3][2]);                              \
            aa[0][3] = fma2(p0, wB.y, aa[0][3]);                              \
            aa[1][3] = fma2(p1, wB.y, aa[1][3]);                              \
            aa[2][3] = fma2(p2, wB.y, aa[2][3]);                              \
            aa[3][3] = fma2(p3, wB.y, aa[3][3]);                              \
            aa[0][4] = fma2(p0, wC.x, aa[0][4]);                              \
            aa[1][4] = fma2(p1, wC.x, aa[1][4]);                              \
            aa[2][4] = fma2(p2, wC.x, aa[2][4]);                              \
            aa[3][4] = fma2(p3, wC.x, aa[3][4]);                              \
            aa[0][5] = fma2(p0, wC.y, aa[0][5]);                              \
            aa[1][5] = fma2(p1, wC.y, aa[1][5]);                              \
            aa[2][5] = fma2(p2, wC.y, aa[2][5]);                              \
            aa[3][5] = fma2(p3, wC.y, aa[3][5]);                              \
        }                                                                     \
    } while (0)

        {
            int4 qA0 = __ldg(xg + 0);
            qB_cur  = __ldg(xg + 1);
            qA_next = __ldg(xg + 2);
            LOADE(eA, qA0);
        }
#pragma unroll 1
        for (int io = 0; io < 256; io += 8) {
            const int j = io >> 2;
            LOADE(eB, qB_cur);
            qB_next = __ldg(xg + ((j + 3 < 64) ? j + 3 : 0));
            COMPUTE4(eA, io);
            LOADE(eA, qA_next);
            qA_nn = __ldg(xg + ((j + 4 < 64) ? j + 4 : 0));
            COMPUTE4(eB, io + 4);
            qB_cur = qB_next;
            qA_next = qA_nn;
        }
#undef LOADE
#undef COMPUTE4

        float* dstb = (py == 0 ? g_pre0 : g_pre1) +
                      ((size_t)b * SEQL + 4 * lane) * NH;
#pragma unroll
        for (int sp = 0; sp < 4; sp++) {
            ulonglong2* d = (ulonglong2*)(dstb + (size_t)sp * NH);
            ulonglong2 v;
            v.x = aa[sp][0]; v.y = aa[sp][1]; d[0] = v;
            v.x = aa[sp][2]; v.y = aa[sp][3]; d[1] = v;
            v.x = aa[sp][4]; v.y = aa[sp][5]; d[2] = v;
        }

        __syncthreads();              // all block stores issued
        if (tid == 0) {
            __threadfence();          // order stores before flag
            atomicAdd(&g_flag[bid >> 2], 1);
        }
        return;
    }

    // ==================== SCAN consumer ====================
    float* ws   = (float*)sraw;                  // 24 KB  w_ih_r [h][i]
    float* e127 = (float*)(sraw + 24576);        // 2 KB
    float* stg  = (float*)(sraw + 26624);        // 12 KB [buf][half][b*96]

    const int g = bid - NPRE;
    for (int t = tid; t < NH * INS; t += 128) ws[t] = wir[t];
    for (int t = tid; t < INS; t += 128)
        e127[t] = emb[(size_t)t * SEQL + (SEQL - 1)];
    __syncthreads();

    const int bslot = tid >> 4;
    const int b = g * 8 + bslot;
    const int hl = tid & 15;
    const int hc = hl < NH ? hl : 0;
    const int* xrow = x + (size_t)b * INS;

    // ---- h_bwd (independent of pre; runs while producers finish) ----
    float hb;
    {
        float acc[NH];
#pragma unroll
        for (int h = 0; h < NH; h++) acc[h] = 0.f;
#pragma unroll 1
        for (int k = 0; k < 32; k += 8) {
            int idv[8];
#pragma unroll
            for (int j = 0; j < 8; j++) idv[j] = xrow[hl + 16 * (k + j)];
#pragma unroll
            for (int j = 0; j < 8; j++) {
                float e = e127[idv[j]];
                const int i = hl + 16 * (k + j);
#pragma unroll
                for (int h = 0; h < NH; h++)
                    acc[h] = fmaf(e, ws[h * INS + i], acc[h]);
            }
        }
        float mine = 0.f;
#pragma unroll
        for (int h = 0; h < NH; h++) {
            float v = acc[h];
#pragma unroll
            for (int o = 8; o; o >>= 1)
                v += __shfl_xor_sync(0xffffffffu, v, o, 16);
            if (h == hl) mine = v;
        }
        hb = ftanh(mine + bir[hc] + bhr[hc]);
    }

    // ---- acquire: wait for this group's 4 producer blocks ----
    if (tid == 0) {
        while (atomicAdd(&g_flag[g], 0) < 4) __nanosleep(200);
        __threadfence();
    }
    __syncthreads();

    // ---- forward recurrence, coop-staged chunks of 8 s ----
    float4 ld[3];
#define STAGE_LOAD(chunk)                                                     \
    do {                                                                      \
        _Pragma("unroll")                                                     \
        for (int q = 0; q < 3; q++) {                                         \
            int idx = tid + 128 * q;                                          \
            int half = idx / 192, r = idx - half * 192;                       \
            int sb = r / 24, off = r - sb * 24;                               \
            const float* src = (half ? g_pre1 : g_pre0) +                     \
                ((size_t)(g * 8 + sb) * SEQL + (chunk) * 8) * NH;             \
            ld[q] = *(const float4*)(src + off * 4);                          \
        }                                                                     \
    } while (0)
#define STAGE_STORE(p)                                                        \
    do {                                                                      \
        _Pragma("unroll")                                                     \
        for (int q = 0; q < 3; q++) {                                         \
            int idx = tid + 128 * q;                                          \
            int half = idx / 192, r = idx - half * 192;                       \
            int sb = r / 24, off = r - sb * 24;                               \
            *(float4*)(&stg[((p) * 2 + half) * 768 + sb * 96 + off * 4]) =    \
                ld[q];                                                        \
        }                                                                     \
    } while (0)

    STAGE_LOAD(0);
    STAGE_STORE(0);
    __syncthreads();

    float wrow[NH];
#pragma unroll
    for (int j = 0; j < NH; j++) wrow[j] = whh[hc * NH + j];
    const float bias = bih[hc] + bhh[hc];

    float h = 0.f;
#pragma unroll 1
    for (int c = 0; c < 16; c++) {
        const int p = c & 1;
        if (c < 15) STAGE_LOAD(c + 1);
        const float* sA = &stg[(p * 2 + 0) * 768 + bslot * 96 + hc];
        const float* sB = &stg[(p * 2 + 1) * 768 + bslot * 96 + hc];
#pragma unroll
        for (int j = 0; j < 8; j++) {
            float pb = sA[j * NH] + sB[j * NH] + bias;
            float v[NH];
#pragma unroll
            for (int k = 0; k < NH; k++)
                v[k] = __shfl_sync(0xffffffffu, h, k, 16);
            float t0 = fmaf(v[0], wrow[0], pb);
            float t1 = v[1] * wrow[1];
            float t2 = v[2] * wrow[2];
#pragma unroll
            for (int k = 3; k < NH; k += 3) {
                t0 = fmaf(v[k    ], wrow[k    ], t0);
                t1 = fmaf(v[k + 1], wrow[k + 1], t1);
                t2 = fmaf(v[k + 2], wrow[k + 2], t2);
            }
            h = ftanh(t0 + t1 + t2);
        }
        if (c < 15) STAGE_STORE(1 - p);
        __syncthreads();
    }
#undef STAGE_LOAD
#undef STAGE_STORE

    // ---- FC epilogue ----
    float v[NH], hbv[NH];
#pragma unroll
    for (int j = 0; j < NH; j++) {
        v[j]   = __shfl_sync(0xffffffffu, h,  j, 16);
        hbv[j] = __shfl_sync(0xffffffffu, hb, j, 16);
    }
    if (hl < NOUT) {
        float o = fcb[hl];
#pragma unroll
        for (int j = 0; j < NH; j++) o = fmaf(v[j], fcw[hl * 2 * NH + j], o);
#pragma unroll
        for (int j = 0; j < NH; j++) o = fmaf(hbv[j], fcw[hl * 2 * NH + NH + j], o);
        out[b * NOUT + hl] = o;
    }

    // ---- replay-safe flag reset (next launch's producers start from 0) ----
    __syncthreads();
    if (tid == 0) atomicExch(&g_flag[g], 0);
}

// ---------------------------------------------------------------------------
extern "C" void kernel_launch(void* const* d_in, const int* in_sizes, int n_in,
                              void* d_out, int out_size) {
    const int*   x      = (const int*)  d_in[0];
    const float* emb    = (const float*)d_in[1];
    const float* w_ih_f = (const float*)d_in[2];
    const float* w_hh_f = (const float*)d_in[3];
    const float* b_ih_f = (const float*)d_in[4];
    const float* b_hh_f = (const float*)d_in[5];
    const float* w_ih_r = (const float*)d_in[6];
    // d_in[7] = w_hh_r (unused: reference consumes only the one-step reverse state)
    const float* b_ih_r = (const float*)d_in[8];
    const float* b_hh_r = (const float*)d_in[9];
    const float* fc_w   = (const float*)d_in[10];
    const float* fc_b   = (const float*)d_in[11];
    float* out = (float*)d_out;

    mega_kernel<<<NPRE + NSCAN, 128>>>(x, emb, w_ih_f,
                                       w_ih_r, b_ih_r, b_hh_r,
                                       w_hh_f, b_ih_f, b_hh_f,
                                       fc_w, fc_b, out);
}

// round 16
// speedup vs baseline: 1.0207x; 1.0207x over previous
#include <cuda_runtime.h>
#include <cstdint>

#define NB   2048
#define INS  512
#define SEQL 128
#define NH   12
#define NOUT 3

// scratch (allocation-free contract: __device__ globals)
__device__ float g_pre0[(size_t)NB * SEQL * NH];   // [b][s][h], K-half 0
__device__ float g_pre1[(size_t)NB * SEQL * NH];   // [b][s][h], K-half 1

__device__ __forceinline__ unsigned long long fma2(unsigned long long a,
                                                   unsigned long long b,
                                                   unsigned long long c) {
    unsigned long long d;
    asm("fma.rn.f32x2 %0, %1, %2, %3;" : "=l"(d) : "l"(a), "l"(b), "l"(c));
    return d;
}
__device__ __forceinline__ unsigned long long pk2(float f) {
    unsigned long long u;
    asm("mov.b64 %0, {%1, %1};" : "=l"(u) : "f"(f));
    return u;
}
__device__ __forceinline__ float ftanh(float x) {
    float e = __expf(2.0f * x);
    return 1.0f - __fdividef(2.0f, e + 1.0f);
}

// ---------------------------------------------------------------------------
// Kernel 1: pre_y[b,s,h] = sum_{i in K-half y} emb[x[b,i], s] * w_ih_f[h,i]
// (R10/R14 exactly: measured ~67us.)
// ---------------------------------------------------------------------------
extern "C" __global__ void __launch_bounds__(128, 5)
pre_kernel(const int* __restrict__ x, const float* __restrict__ emb,
           const float* __restrict__ wih) {
    __shared__ float2 w2[256 * 6];   // 12 KB: this K-half only

    const int tid = threadIdx.x;
    const int y = blockIdx.y;            // K-half
    const int ibase = y * 256;

    for (int t = tid; t < 256 * 6; t += 128) {
        int il = t & 255;
        int k = t >> 8;                  // 0..5
        w2[il * 6 + k] = make_float2(wih[(2 * k) * INS + ibase + il],
                                     wih[(2 * k + 1) * INS + ibase + il]);
    }
    __syncthreads();

    const int warp = tid >> 5;
    const int lane = tid & 31;
    const int b = blockIdx.x * 4 + warp;
    const int4* xg = (const int4*)(x + (size_t)b * INS) + y * 64;
    const float* ebase = emb + 4 * lane;

    unsigned long long aa[4][6];         // [s-slot][h-pair]
#pragma unroll
    for (int sp = 0; sp < 4; sp++)
#pragma unroll
        for (int k = 0; k < 6; k++) aa[sp][k] = 0ull;

    float4 eA[4], eB[4];
    int4 qB_cur, qA_next, qB_next, qA_nn;

#define LOADE(buf, q)                                                         \
    do {                                                                      \
        buf[0] = *(const float4*)(ebase + ((unsigned)(q).x << 7));            \
        buf[1] = *(const float4*)(ebase + ((unsigned)(q).y << 7));            \
        buf[2] = *(const float4*)(ebase + ((unsigned)(q).z << 7));            \
        buf[3] = *(const float4*)(ebase + ((unsigned)(q).w << 7));            \
    } while (0)

#define COMPUTE4(buf, bi)                                                     \
    do {                                                                      \
        _Pragma("unroll")                                                     \
        for (int u = 0; u < 4; u++) {                                         \
            unsigned long long p0 = pk2(buf[u].x);                            \
            unsigned long long p1 = pk2(buf[u].y);                            \
            unsigned long long p2 = pk2(buf[u].z);                            \
            unsigned long long p3 = pk2(buf[u].w);                            \
            const ulonglong2* wv =                                            \
                (const ulonglong2*)(w2 + (unsigned)((bi) + u) * 6);           \
            ulonglong2 wA = wv[0], wB = wv[1], wC = wv[2];                    \
            aa[0][0] = fma2(p0, wA.x, aa[0][0]);                              \
            aa[1][0] = fma2(p1, wA.x, aa[1][0]);                              \
            aa[2][0] = fma2(p2, wA.x, aa[2][0]);                              \
            aa[3][0] = fma2(p3, wA.x, aa[3][0]);                              \
            aa[0][1] = fma2(p0, wA.y, aa[0][1]);                              \
            aa[1][1] = fma2(p1, wA.y, aa[1][1]);                              \
            aa[2][1] = fma2(p2, wA.y, aa[2][1]);                              \
            aa[3][1] = fma2(p3, wA.y, aa[3][1]);                              \
            aa[0][2] = fma2(p0, wB.x, aa[0][2]);                              \
            aa[1][2] = fma2(p1, wB.x, aa[1][2]);                              \
            aa[2][2] = fma2(p2, wB.x, aa[2][2]);                              \
            aa[3][2] = fma2(p3, wB.x, aa[3][2]);                              \
            aa[0][3] = fma2(p0, wB.y, aa[0][3]);                              \
            aa[1][3] = fma2(p1, wB.y, aa[1][3]);                              \
            aa[2][3] = fma2(p2, wB.y, aa[2][3]);                              \
            aa[3][3] = fma2(p3, wB.y, aa[3][3]);                              \
            aa[0][4] = fma2(p0, wC.x, aa[0][4]);                              \
            aa[1][4] = fma2(p1, wC.x, aa[1][4]);                              \
            aa[2][4] = fma2(p2, wC.x, aa[2][4]);                              \
            aa[3][4] = fma2(p3, wC.x, aa[3][4]);                              \
            aa[0][5] = fma2(p0, wC.y, aa[0][5]);                              \
            aa[1][5] = fma2(p1, wC.y, aa[1][5]);                              \
            aa[2][5] = fma2(p2, wC.y, aa[2][5]);                              \
            aa[3][5] = fma2(p3, wC.y, aa[3][5]);                              \
        }                                                                     \
    } while (0)

    {
        int4 qA0 = __ldg(xg + 0);
        qB_cur  = __ldg(xg + 1);
        qA_next = __ldg(xg + 2);
        LOADE(eA, qA0);
    }

#pragma unroll 1
    for (int io = 0; io < 256; io += 8) {
        const int j = io >> 2;
        LOADE(eB, qB_cur);
        qB_next = __ldg(xg + ((j + 3 < 64) ? j + 3 : 0));
        COMPUTE4(eA, io);
        LOADE(eA, qA_next);
        qA_nn = __ldg(xg + ((j + 4 < 64) ? j + 4 : 0));
        COMPUTE4(eB, io + 4);
        qB_cur = qB_next;
        qA_next = qA_nn;
    }
#undef LOADE
#undef COMPUTE4

    float* dstb = (y == 0 ? g_pre0 : g_pre1) +
                  ((size_t)b * SEQL + 4 * lane) * NH;
#pragma unroll
    for (int sp = 0; sp < 4; sp++) {
        ulonglong2* d = (ulonglong2*)(dstb + (size_t)sp * NH);
        ulonglong2 v;
        v.x = aa[sp][0]; v.y = aa[sp][1]; d[0] = v;
        v.x = aa[sp][2]; v.y = aa[sp][3]; d[1] = v;
        v.x = aa[sp][4]; v.y = aa[sp][5]; d[2] = v;
    }
}

// ---------------------------------------------------------------------------
// Kernel 2: scan + fused h_bwd + FC, ILP-2.
// 64-thread blocks, grid 256 (>=148 SMs): 4 slots x 16 lanes, each slot runs
// TWO independent chains (batches 8g+2sl, 8g+2sl+1). Chain A's shfl/tanh
// latency overlaps chain B's fma work — the serial-step critical path that
// pinned 3 scan designs at ~33us. Coop smem staging (6 float4/thread/chunk).
// ---------------------------------------------------------------------------
extern "C" __global__ void __launch_bounds__(64)
scan_kernel(const int* __restrict__ x, const float* __restrict__ emb,
            const float* __restrict__ wir, const float* __restrict__ bir,
            const float* __restrict__ bhr,
            const float* __restrict__ whh, const float* __restrict__ bih,
            const float* __restrict__ bhh, const float* __restrict__ fcw,
            const float* __restrict__ fcb, float* __restrict__ out) {
    __shared__ float ws[NH * INS];            // 24 KB  w_ih_r [h][i]
    __shared__ float e127[INS];               // 2 KB
    __shared__ __align__(16) float stg[2][1536]; // 12 KB [buf][half*768+sb*96+..]

    const int tid = threadIdx.x;
    for (int t = tid; t < NH * INS; t += 64) ws[t] = wir[t];
    for (int t = tid; t < INS; t += 64)
        e127[t] = emb[(size_t)t * SEQL + (SEQL - 1)];

    const int slot = tid >> 4;                // 0..3
    const int hl = tid & 15;
    const int hc = hl < NH ? hl : 0;
    const int bA = blockIdx.x * 8 + slot * 2;
    const int bB = bA + 1;

    // staging: thread covers float4 idx tid + 64q, q=0..5 (384 total)
    float4 ld[6];
#define STAGE_LOAD(chunk)                                                     \
    do {                                                                      \
        _Pragma("unroll")                                                     \
        for (int q = 0; q < 6; q++) {                                         \
            int idx = tid + 64 * q;                                           \
            int half = idx / 192, r = idx - half * 192;                       \
            int sb = r / 24, off = r - sb * 24;                               \
            const float* src = (half ? g_pre1 : g_pre0) +                     \
                ((size_t)(blockIdx.x * 8 + sb) * SEQL + (chunk) * 8) * NH;    \
            ld[q] = *(const float4*)(src + off * 4);                          \
        }                                                                     \
    } while (0)
#define STAGE_STORE(p)                                                        \
    do {                                                                      \
        _Pragma("unroll")                                                     \
        for (int q = 0; q < 6; q++) {                                         \
            int idx = tid + 64 * q;                                           \
            int half = idx / 192, r = idx - half * 192;                       \
            int sb = r / 24, off = r - sb * 24;                               \
            *(float4*)(&stg[p][half * 768 + sb * 96 + off * 4]) = ld[q];      \
        }                                                                     \
    } while (0)

    STAGE_LOAD(0);
    STAGE_STORE(0);
    __syncthreads();

    // ---- fused h_bwd for BOTH chains (lane hl covers i = hl + 16k) ----
    float hbA, hbB;
    {
        float aAcc[NH], bAcc[NH];
#pragma unroll
        for (int h = 0; h < NH; h++) { aAcc[h] = 0.f; bAcc[h] = 0.f; }
        const int* xrA = x + (size_t)bA * INS;
        const int* xrB = x + (size_t)bB * INS;
#pragma unroll 1
        for (int k = 0; k < 32; k += 8) {
            int ivA[8], ivB[8];
#pragma unroll
            for (int j = 0; j < 8; j++) {
                ivA[j] = xrA[hl + 16 * (k + j)];
                ivB[j] = xrB[hl + 16 * (k + j)];
            }
#pragma unroll
            for (int j = 0; j < 8; j++) {
                float eA = e127[ivA[j]];
                float eB = e127[ivB[j]];
                const int i = hl + 16 * (k + j);
#pragma unroll
                for (int h = 0; h < NH; h++) {
                    float w = ws[h * INS + i];
                    aAcc[h] = fmaf(eA, w, aAcc[h]);
                    bAcc[h] = fmaf(eB, w, bAcc[h]);
                }
            }
        }
        float mA = 0.f, mB = 0.f;
#pragma unroll
        for (int h = 0; h < NH; h++) {
            float vA = aAcc[h], vB = bAcc[h];
#pragma unroll
            for (int o = 8; o; o >>= 1) {
                vA += __shfl_xor_sync(0xffffffffu, vA, o, 16);
                vB += __shfl_xor_sync(0xffffffffu, vB, o, 16);
            }
            if (h == hl) { mA = vA; mB = vB; }
        }
        hbA = ftanh(mA + bir[hc] + bhr[hc]);
        hbB = ftanh(mB + bir[hc] + bhr[hc]);
    }

    // ---- forward recurrence, 2 chains, 16 chunks of 8 s ----
    float wrow[NH];
#pragma unroll
    for (int j = 0; j < NH; j++) wrow[j] = whh[hc * NH + j];
    const float bias = bih[hc] + bhh[hc];

    float hA = 0.f, hB = 0.f;
#pragma unroll 1
    for (int c = 0; c < 16; c++) {
        const int p = c & 1;
        if (c < 15) STAGE_LOAD(c + 1);
        const float* s0A = &stg[p][0 * 768 + (slot * 2) * 96 + hc];
        const float* s1A = &stg[p][1 * 768 + (slot * 2) * 96 + hc];
        const float* s0B = s0A + 96;
        const float* s1B = s1A + 96;
#pragma unroll
        for (int j = 0; j < 8; j++) {
            float pbA = s0A[j * NH] + s1A[j * NH] + bias;
            float pbB = s0B[j * NH] + s1B[j * NH] + bias;
            float vA[NH], vB[NH];
#pragma unroll
            for (int k = 0; k < NH; k++) {
                vA[k] = __shfl_sync(0xffffffffu, hA, k, 16);
                vB[k] = __shfl_sync(0xffffffffu, hB, k, 16);
            }
            float tA0 = fmaf(vA[0], wrow[0], pbA);
            float tB0 = fmaf(vB[0], wrow[0], pbB);
            float tA1 = vA[1] * wrow[1], tB1 = vB[1] * wrow[1];
            float tA2 = vA[2] * wrow[2], tB2 = vB[2] * wrow[2];
#pragma unroll
            for (int k = 3; k < NH; k += 3) {
                tA0 = fmaf(vA[k    ], wrow[k    ], tA0);
                tB0 = fmaf(vB[k    ], wrow[k    ], tB0);
                tA1 = fmaf(vA[k + 1], wrow[k + 1], tA1);
                tB1 = fmaf(vB[k + 1], wrow[k + 1], tB1);
                tA2 = fmaf(vA[k + 2], wrow[k + 2], tA2);
                tB2 = fmaf(vB[k + 2], wrow[k + 2], tB2);
            }
            hA = ftanh(tA0 + tA1 + tA2);
            hB = ftanh(tB0 + tB1 + tB2);
        }
        if (c < 15) STAGE_STORE(1 - p);
        __syncthreads();
    }
#undef STAGE_LOAD
#undef STAGE_STORE

    // ---- FC epilogue, both chains ----
    float vA[NH], vB[NH], hA_v[NH], hB_v[NH];
#pragma unroll
    for (int j = 0; j < NH; j++) {
        vA[j]   = __shfl_sync(0xffffffffu, hA,  j, 16);
        vB[j]   = __shfl_sync(0xffffffffu, hB,  j, 16);
        hA_v[j] = __shfl_sync(0xffffffffu, hbA, j, 16);
        hB_v[j] = __shfl_sync(0xffffffffu, hbB, j, 16);
    }
    if (hl < NOUT) {
        float oA = fcb[hl], oB = fcb[hl];
#pragma unroll
        for (int j = 0; j < NH; j++) {
            oA = fmaf(vA[j], fcw[hl * 2 * NH + j], oA);
            oB = fmaf(vB[j], fcw[hl * 2 * NH + j], oB);
        }
#pragma unroll
        for (int j = 0; j < NH; j++) {
            oA = fmaf(hA_v[j], fcw[hl * 2 * NH + NH + j], oA);
            oB = fmaf(hB_v[j], fcw[hl * 2 * NH + NH + j], oB);
        }
        out[bA * NOUT + hl] = oA;
        out[bB * NOUT + hl] = oB;
    }
}

// ---------------------------------------------------------------------------
extern "C" void kernel_launch(void* const* d_in, const int* in_sizes, int n_in,
                              void* d_out, int out_size) {
    const int*   x      = (const int*)  d_in[0];
    const float* emb    = (const float*)d_in[1];
    const float* w_ih_f = (const float*)d_in[2];
    const float* w_hh_f = (const float*)d_in[3];
    const float* b_ih_f = (const float*)d_in[4];
    const float* b_hh_f = (const float*)d_in[5];
    const float* w_ih_r = (const float*)d_in[6];
    // d_in[7] = w_hh_r (unused: reference consumes only the one-step reverse state)
    const float* b_ih_r = (const float*)d_in[8];
    const float* b_hh_r = (const float*)d_in[9];
    const float* fc_w   = (const float*)d_in[10];
    const float* fc_b   = (const float*)d_in[11];
    float* out = (float*)d_out;

    pre_kernel<<<dim3(NB / 4, 2), 128>>>(x, emb, w_ih_f);
    scan_kernel<<<NB / 8, 64>>>(x, emb, w_ih_r, b_ih_r, b_hh_r,
                                w_hh_f, b_ih_f, b_hh_f, fc_w, fc_b, out);
}

// round 17
// speedup vs baseline: 1.1007x; 1.0783x over previous
#include <cuda_runtime.h>
#include <cstdint>

#define NB   2048
#define INS  512
#define SEQL 128
#define NH   12
#define NOUT 3

// scratch (allocation-free contract: __device__ globals)
__device__ float g_pre0[(size_t)NB * SEQL * NH];   // [b][s][h], K-half 0
__device__ float g_pre1[(size_t)NB * SEQL * NH];   // [b][s][h], K-half 1

__device__ __forceinline__ unsigned long long fma2(unsigned long long a,
                                                   unsigned long long b,
                                                   unsigned long long c) {
    unsigned long long d;
    asm("fma.rn.f32x2 %0, %1, %2, %3;" : "=l"(d) : "l"(a), "l"(b), "l"(c));
    return d;
}
__device__ __forceinline__ unsigned long long pk2(float f) {
    unsigned long long u;
    asm("mov.b64 %0, {%1, %1};" : "=l"(u) : "f"(f));
    return u;
}
__device__ __forceinline__ float ftanh(float x) {           // exact-ish (h_bwd)
    float e = __expf(2.0f * x);
    return 1.0f - __fdividef(2.0f, e + 1.0f);
}
__device__ __forceinline__ float tanha(float x) {           // HW MUFU.TANH
    float y;
    asm("tanh.approx.f32 %0, %1;" : "=f"(y) : "f"(x));
    return y;
}

// ---------------------------------------------------------------------------
// Kernel 1: pre_y[b,s,h] = sum_{i in K-half y} emb[x[b,i], s] * w_ih_f[h,i]
// (R10/R14 exactly: measured ~67us.)
// ---------------------------------------------------------------------------
extern "C" __global__ void __launch_bounds__(128, 5)
pre_kernel(const int* __restrict__ x, const float* __restrict__ emb,
           const float* __restrict__ wih) {
    __shared__ float2 w2[256 * 6];   // 12 KB: this K-half only

    const int tid = threadIdx.x;
    const int y = blockIdx.y;            // K-half
    const int ibase = y * 256;

    for (int t = tid; t < 256 * 6; t += 128) {
        int il = t & 255;
        int k = t >> 8;                  // 0..5
        w2[il * 6 + k] = make_float2(wih[(2 * k) * INS + ibase + il],
                                     wih[(2 * k + 1) * INS + ibase + il]);
    }
    __syncthreads();

    const int warp = tid >> 5;
    const int lane = tid & 31;
    const int b = blockIdx.x * 4 + warp;
    const int4* xg = (const int4*)(x + (size_t)b * INS) + y * 64;
    const float* ebase = emb + 4 * lane;

    unsigned long long aa[4][6];         // [s-slot][h-pair]
#pragma unroll
    for (int sp = 0; sp < 4; sp++)
#pragma unroll
        for (int k = 0; k < 6; k++) aa[sp][k] = 0ull;

    float4 eA[4], eB[4];
    int4 qB_cur, qA_next, qB_next, qA_nn;

#define LOADE(buf, q)                                                         \
    do {                                                                      \
        buf[0] = *(const float4*)(ebase + ((unsigned)(q).x << 7));            \
        buf[1] = *(const float4*)(ebase + ((unsigned)(q).y << 7));            \
        buf[2] = *(const float4*)(ebase + ((unsigned)(q).z << 7));            \
        buf[3] = *(const float4*)(ebase + ((unsigned)(q).w << 7));            \
    } while (0)

#define COMPUTE4(buf, bi)                                                     \
    do {                                                                      \
        _Pragma("unroll")                                                     \
        for (int u = 0; u < 4; u++) {                                         \
            unsigned long long p0 = pk2(buf[u].x);                            \
            unsigned long long p1 = pk2(buf[u].y);                            \
            unsigned long long p2 = pk2(buf[u].z);                            \
            unsigned long long p3 = pk2(buf[u].w);                            \
            const ulonglong2* wv =                                            \
                (const ulonglong2*)(w2 + (unsigned)((bi) + u) * 6);           \
            ulonglong2 wA = wv[0], wB = wv[1], wC = wv[2];                    \
            aa[0][0] = fma2(p0, wA.x, aa[0][0]);                              \
            aa[1][0] = fma2(p1, wA.x, aa[1][0]);                              \
            aa[2][0] = fma2(p2, wA.x, aa[2][0]);                              \
            aa[3][0] = fma2(p3, wA.x, aa[3][0]);                              \
            aa[0][1] = fma2(p0, wA.y, aa[0][1]);                              \
            aa[1][1] = fma2(p1, wA.y, aa[1][1]);                              \
            aa[2][1] = fma2(p2, wA.y, aa[2][1]);                              \
            aa[3][1] = fma2(p3, wA.y, aa[3][1]);                              \
            aa[0][2] = fma2(p0, wB.x, aa[0][2]);                              \
            aa[1][2] = fma2(p1, wB.x, aa[1][2]);                              \
            aa[2][2] = fma2(p2, wB.x, aa[2][2]);                              \
            aa[3][2] = fma2(p3, wB.x, aa[3][2]);                              \
            aa[0][3] = fma2(p0, wB.y, aa[0][3]);                              \
            aa[1][3] = fma2(p1, wB.y, aa[1][3]);                              \
            aa[2][3] = fma2(p2, wB.y, aa[2][3]);                              \
            aa[3][3] = fma2(p3, wB.y, aa[3][3]);                              \
            aa[0][4] = fma2(p0, wC.x, aa[0][4]);                              \
            aa[1][4] = fma2(p1, wC.x, aa[1][4]);                              \
            aa[2][4] = fma2(p2, wC.x, aa[2][4]);                              \
            aa[3][4] = fma2(p3, wC.x, aa[3][4]);                              \
            aa[0][5] = fma2(p0, wC.y, aa[0][5]);                              \
            aa[1][5] = fma2(p1, wC.y, aa[1][5]);                              \
            aa[2][5] = fma2(p2, wC.y, aa[2][5]);                              \
            aa[3][5] = fma2(p3, wC.y, aa[3][5]);                              \
        }                                                                     \
    } while (0)

    {
        int4 qA0 = __ldg(xg + 0);
        qB_cur  = __ldg(xg + 1);
        qA_next = __ldg(xg + 2);
        LOADE(eA, qA0);
    }

#pragma unroll 1
    for (int io = 0; io < 256; io += 8) {
        const int j = io >> 2;
        LOADE(eB, qB_cur);
        qB_next = __ldg(xg + ((j + 3 < 64) ? j + 3 : 0));
        COMPUTE4(eA, io);
        LOADE(eA, qA_next);
        qA_nn = __ldg(xg + ((j + 4 < 64) ? j + 4 : 0));
        COMPUTE4(eB, io + 4);
        qB_cur = qB_next;
        qA_next = qA_nn;
    }
#undef LOADE
#undef COMPUTE4

    float* dstb = (y == 0 ? g_pre0 : g_pre1) +
                  ((size_t)b * SEQL + 4 * lane) * NH;
#pragma unroll
    for (int sp = 0; sp < 4; sp++) {
        ulonglong2* d = (ulonglong2*)(dstb + (size_t)sp * NH);
        ulonglong2 v;
        v.x = aa[sp][0]; v.y = aa[sp][1]; d[0] = v;
        v.x = aa[sp][2]; v.y = aa[sp][3]; d[1] = v;
        v.x = aa[sp][4]; v.y = aa[sp][5]; d[2] = v;
    }
}

// ---------------------------------------------------------------------------
// Kernel 2: scan + fused h_bwd + FC (R11 form, best measured 32.5us), with
// the recurrence tanh replaced by HW MUFU.TANH (tanh.approx.f32): cuts the
// ~50cyc exp/div sequence to one 16cyc MUFU on the serial critical path
// that four load-scheme variants proved is the binding constraint.
// h_bwd keeps exact ftanh (one step, off the chain).
// 128 thr = 8 batches (16 lanes each); depth-8 reg double buffering.
// ---------------------------------------------------------------------------
extern "C" __global__ void __launch_bounds__(128)
scan_kernel(const int* __restrict__ x, const float* __restrict__ emb,
            const float* __restrict__ wir, const float* __restrict__ bir,
            const float* __restrict__ bhr,
            const float* __restrict__ whh, const float* __restrict__ bih,
            const float* __restrict__ bhh, const float* __restrict__ fcw,
            const float* __restrict__ fcb, float* __restrict__ out) {
    __shared__ float ws[NH * INS];   // 24 KB  w_ih_r [h][i]
    __shared__ float e127[INS];      // 2 KB   emb[:,127]

    const int tid = threadIdx.x;
    for (int t = tid; t < NH * INS; t += 128) ws[t] = wir[t];
    for (int t = tid; t < INS; t += 128)
        e127[t] = emb[(size_t)t * SEQL + (SEQL - 1)];
    __syncthreads();

    const int b = blockIdx.x * 8 + (tid >> 4);
    const int hl = tid & 15;
    const int hc = hl < NH ? hl : 0;
    const int* xrow = x + (size_t)b * INS;

    // ---- fused h_bwd (lane hl covers i = hl + 16k) ----
    float hb;
    {
        float acc[NH];
#pragma unroll
        for (int h = 0; h < NH; h++) acc[h] = 0.f;
#pragma unroll 1
        for (int k = 0; k < 32; k += 8) {
            int idv[8];
#pragma unroll
            for (int j = 0; j < 8; j++) idv[j] = xrow[hl + 16 * (k + j)];
#pragma unroll
            for (int j = 0; j < 8; j++) {
                float e = e127[idv[j]];
                const int i = hl + 16 * (k + j);
#pragma unroll
                for (int h = 0; h < NH; h++)
                    acc[h] = fmaf(e, ws[h * INS + i], acc[h]);
            }
        }
        float mine = 0.f;
#pragma unroll
        for (int h = 0; h < NH; h++) {
            float v = acc[h];
#pragma unroll
            for (int o = 8; o; o >>= 1)
                v += __shfl_xor_sync(0xffffffffu, v, o, 16);
            if (h == hl) mine = v;
        }
        hb = ftanh(mine + bir[hc] + bhr[hc]);
    }

    // ---- forward recurrence, depth-8 chunked double buffering ----
    float wrow[NH];
#pragma unroll
    for (int j = 0; j < NH; j++) wrow[j] = whh[hc * NH + j];
    const float bias = bih[hc] + bhh[hc];

    const float* psA = g_pre0 + (size_t)b * SEQL * NH + hc;
    const float* psB = g_pre1 + (size_t)b * SEQL * NH + hc;

    float rA[8], rB[8];
#pragma unroll
    for (int j = 0; j < 8; j++) {
        rA[j] = psA[(size_t)j * NH];
        rB[j] = psB[(size_t)j * NH];
    }

    float h = 0.f;
#pragma unroll 1
    for (int c = 0; c < 16; c++) {
        float nA[8], nB[8];
        const int nbase = (c + 1) * 8;
#pragma unroll
        for (int j = 0; j < 8; j++) {
            int sl = (nbase + j < SEQL) ? (nbase + j) : 0;
            nA[j] = psA[(size_t)sl * NH];
            nB[j] = psB[(size_t)sl * NH];
        }
#pragma unroll
        for (int j = 0; j < 8; j++) {
            float pb = rA[j] + rB[j] + bias;
            float v[NH];
#pragma unroll
            for (int k = 0; k < NH; k++)
                v[k] = __shfl_sync(0xffffffffu, h, k, 16);
            float t0 = fmaf(v[0], wrow[0], pb);
            float t1 = v[1] * wrow[1];
            float t2 = v[2] * wrow[2];
#pragma unroll
            for (int k = 3; k < NH; k += 3) {
                t0 = fmaf(v[k    ], wrow[k    ], t0);
                t1 = fmaf(v[k + 1], wrow[k + 1], t1);
                t2 = fmaf(v[k + 2], wrow[k + 2], t2);
            }
            h = tanha(t0 + t1 + t2);          // HW MUFU.TANH on the chain
        }
#pragma unroll
        for (int j = 0; j < 8; j++) { rA[j] = nA[j]; rB[j] = nB[j]; }
    }

    // ---- FC epilogue ----
    float v[NH], hbv[NH];
#pragma unroll
    for (int j = 0; j < NH; j++) {
        v[j]   = __shfl_sync(0xffffffffu, h,  j, 16);
        hbv[j] = __shfl_sync(0xffffffffu, hb, j, 16);
    }
    if (hl < NOUT) {
        float o = fcb[hl];
#pragma unroll
        for (int j = 0; j < NH; j++) o = fmaf(v[j], fcw[hl * 2 * NH + j], o);
#pragma unroll
        for (int j = 0; j < NH; j++) o = fmaf(hbv[j], fcw[hl * 2 * NH + NH + j], o);
        out[b * NOUT + hl] = o;
    }
}

// ---------------------------------------------------------------------------
extern "C" void kernel_launch(void* const* d_in, const int* in_sizes, int n_in,
                              void* d_out, int out_size) {
    const int*   x      = (const int*)  d_in[0];
    const float* emb    = (const float*)d_in[1];
    const float* w_ih_f = (const float*)d_in[2];
    const float* w_hh_f = (const float*)d_in[3];
    const float* b_ih_f = (const float*)d_in[4];
    const float* b_hh_f = (const float*)d_in[5];
    const float* w_ih_r = (const float*)d_in[6];
    // d_in[7] = w_hh_r (unused: reference consumes only the one-step reverse state)
    const float* b_ih_r = (const float*)d_in[8];
    const float* b_hh_r = (const float*)d_in[9];
    const float* fc_w   = (const float*)d_in[10];
    const float* fc_b   = (const float*)d_in[11];
    float* out = (float*)d_out;

    pre_kernel<<<dim3(NB / 4, 2), 128>>>(x, emb, w_ih_f);
    scan_kernel<<<NB / 8, 128>>>(x, emb, w_ih_r, b_ih_r, b_hh_r,
                                 w_hh_f, b_ih_f, b_hh_f, fc_w, fc_b, out);
}